// round 6
// baseline (speedup 1.0000x reference)
#include <cuda_runtime.h>
#include <math.h>

#define NTA 512    // ab kernel threads
#define NTG 256    // gather kernel threads
#define RB  16     // rows (classes/codes) per ab block
#define GROWS 2048 // rows per gather block tile

struct Params {
  const int*   obs;
  const float *embed, *W1, *b1, *W2, *b2, *W3, *b3, *Wp, *bp, *codebook;
  const float *Wa, *ba, *Ws, *bs, *Wc1, *bc1, *Wc2, *bc2, *Wc3, *bc3, *Wc4, *bc4;
  float *out_actor, *out_scale, *out_critic, *out_loss, *out_idx;
  int NC, VQN, nClsBlk, B, nRowTiles;
};

// Device-global scratch (no allocation allowed)
__device__ int      g_idx_cls[1024];
__device__ float    g_loss_cls[1024];
__device__ float    g_tbl_actor[512 * 128];
__device__ float    g_tbl_scale[512 * 128];
__device__ float    g_tbl_crit[512];
__device__ float    g_partials[1024];
__device__ unsigned g_ticket;

struct SmemAB {
  float wbuf[2][16384];     // 128 KB double-buffered weights
  float A[RB][128];         // 8 KB
  float Bb[RB][128];        // 8 KB
  float part[3][RB][128];   // 24 KB k-quarter partials
  float dist[RB][512];      // 32 KB
  float znorm[RB];
};                          // ~200 KB

struct SmemG {
  float sA[512 * 32];       // 64 KB actor table slice
  float sS[512 * 32];       // 64 KB scale table slice
  short codes[GROWS];       // 4 KB
  float red[8];
  float s[NTG];
  int   lastblk;
};                          // ~133 KB

__device__ __forceinline__ float sigf(float x) { return 1.0f / (1.0f + expf(-x)); }

// ---------------- cp.async helpers ----------------
__device__ __forceinline__ void cpa16(void* sdst, const void* gsrc) {
  unsigned s = (unsigned)__cvta_generic_to_shared(sdst);
  asm volatile("cp.async.cg.shared.global [%0], [%1], 16;\n" :: "r"(s), "l"(gsrc));
}
__device__ __forceinline__ void cpa_commit() { asm volatile("cp.async.commit_group;\n"); }
__device__ __forceinline__ void cpa_wait0()  { asm volatile("cp.async.wait_group 0;\n"); }

__device__ __forceinline__ void pf(float* dst, const float* src, int nfloats) {
  const int n4 = nfloats >> 2;
  for (int i = threadIdx.x; i < n4; i += NTA)
    cpa16(reinterpret_cast<float4*>(dst) + i, reinterpret_cast<const float4*>(src) + i);
  cpa_commit();
}

__device__ __forceinline__ float comp4(const float4& v, int j) {
  return j == 0 ? v.x : j == 1 ? v.y : j == 2 ? v.z : v.w;
}

// ------- RB-row GEMM layer, 4-row x k-quarter warp tiling (16 warps) -------
// warp w: rowgroup rg = w&3 (rows 4rg..4rg+3), kquarter kq = w>>2.
// lane = float4 column group (N/4 groups; lanes >= N/4 idle for N<128).
// ACT: 0 linear, 1 relu, 2 sigmoid, 3 sigmoid+1e-8
template<int K, int N, int ACT>
__device__ __forceinline__ void layerQ(const float (*__restrict__ in)[128],
                                       const float* __restrict__ wb,
                                       const float* __restrict__ bias_g,
                                       float (*__restrict__ outs)[128],
                                       float* __restrict__ outg, int grow0,
                                       SmemAB& sm)
{
  const int tid = threadIdx.x, warp = tid >> 5, lane = tid & 31;
  const int rg = warp & 3, kq = warp >> 2;
  const int r0 = rg * 4;
  constexpr int NG = N / 4;
  const bool active = lane < NG;

  float4 acc[4];
  #pragma unroll
  for (int r = 0; r < 4; r++) acc[r] = make_float4(0.f, 0.f, 0.f, 0.f);

  if (active) {
    const float4* w4 = reinterpret_cast<const float4*>(wb) + lane;
    const int kbeg = kq * (K / 4), kend = kbeg + (K / 4);
    #pragma unroll 2
    for (int k = kbeg; k < kend; k += 4) {
      float4 a[4];
      #pragma unroll
      for (int r = 0; r < 4; r++)
        a[r] = *reinterpret_cast<const float4*>(&in[r0 + r][k]);   // broadcast
      #pragma unroll
      for (int j = 0; j < 4; j++) {
        const float4 w = w4[(size_t)(k + j) * NG];
        #pragma unroll
        for (int r = 0; r < 4; r++) {
          const float aj = comp4(a[r], j);
          acc[r].x = fmaf(aj, w.x, acc[r].x);
          acc[r].y = fmaf(aj, w.y, acc[r].y);
          acc[r].z = fmaf(aj, w.z, acc[r].z);
          acc[r].w = fmaf(aj, w.w, acc[r].w);
        }
      }
    }
  }
  if (kq > 0 && active) {
    #pragma unroll
    for (int r = 0; r < 4; r++)
      *reinterpret_cast<float4*>(&sm.part[kq - 1][r0 + r][lane * 4]) = acc[r];
  }
  __syncthreads();
  if (kq == 0 && active) {
    const float4 bb = __ldg(reinterpret_cast<const float4*>(bias_g) + lane);
    #pragma unroll
    for (int r = 0; r < 4; r++) {
      const float4 p1 = *reinterpret_cast<const float4*>(&sm.part[0][r0 + r][lane * 4]);
      const float4 p2 = *reinterpret_cast<const float4*>(&sm.part[1][r0 + r][lane * 4]);
      const float4 p3 = *reinterpret_cast<const float4*>(&sm.part[2][r0 + r][lane * 4]);
      float v[4] = {((acc[r].x + p1.x) + p2.x) + p3.x + bb.x,
                    ((acc[r].y + p1.y) + p2.y) + p3.y + bb.y,
                    ((acc[r].z + p1.z) + p2.z) + p3.z + bb.z,
                    ((acc[r].w + p1.w) + p2.w) + p3.w + bb.w};
      #pragma unroll
      for (int j = 0; j < 4; j++) {
        if (ACT == 1) v[j] = v[j] > 0.f ? v[j] : 0.f;
        if (ACT == 2 || ACT == 3) v[j] = sigf(v[j]);
        if (ACT == 3) v[j] += 1e-8f;
      }
      const float4 o = make_float4(v[0], v[1], v[2], v[3]);
      if (outs) *reinterpret_cast<float4*>(&outs[r0 + r][lane * 4]) = o;
      if (outg)
        reinterpret_cast<float4*>(outg)[(size_t)(grow0 + r0 + r) * NG + lane] = o;
    }
  }
  __syncthreads();
}

__global__ void __launch_bounds__(NTA, 1) acsq_ab(Params p)
{
  extern __shared__ char smraw[];
  SmemAB& sm = *reinterpret_cast<SmemAB*>(smraw);
  const int tid = threadIdx.x;

  if ((int)blockIdx.x < p.nClsBlk) {
    // ================= CLASS PATH: 16 classes =================
    const int c0 = blockIdx.x * RB;

    pf(sm.wbuf[0], p.W1, 128 * 128);
    {   // embed gather: 16 rows x 32 float4
      const int r = tid >> 5, col = tid & 31, cls = c0 + r;
      float4 v = make_float4(0.f, 0.f, 0.f, 0.f);
      if (cls < p.NC)
        v = __ldg(reinterpret_cast<const float4*>(p.embed + (size_t)cls * 128) + col);
      reinterpret_cast<float4*>(sm.A[r])[col] = v;
    }
    cpa_wait0(); __syncthreads();

    pf(sm.wbuf[1], p.W2, 128 * 128);
    layerQ<128, 128, 1>(sm.A, sm.wbuf[0], p.b1, sm.Bb, nullptr, 0, sm);
    cpa_wait0(); __syncthreads();

    pf(sm.wbuf[0], p.W3, 128 * 128);
    layerQ<128, 128, 1>(sm.Bb, sm.wbuf[1], p.b2, sm.A, nullptr, 0, sm);
    cpa_wait0(); __syncthreads();

    pf(sm.wbuf[1], p.Wp, 128 * 64);
    layerQ<128, 128, 1>(sm.A, sm.wbuf[0], p.b3, sm.Bb, nullptr, 0, sm);
    cpa_wait0(); __syncthreads();

    layerQ<128, 64, 0>(sm.Bb, sm.wbuf[1], p.bp, sm.A, nullptr, 0, sm);
    // z in A[:,0:64]
    if (tid < RB) {
      float s = 0.f;
      #pragma unroll
      for (int k = 0; k < 64; k++) s = fmaf(sm.A[tid][k], sm.A[tid][k], s);
      sm.znorm[tid] = s;
    }
    __syncthreads();

    // ---- VQ distances: one thread per code ----
    {
      const int cc = tid;
      if (cc < p.VQN) {
        float4 cb[16];
        const float4* cp = reinterpret_cast<const float4*>(p.codebook + (size_t)cc * 64);
        #pragma unroll
        for (int q = 0; q < 16; q++) cb[q] = __ldg(cp + q);
        float cn = 0.f;
        #pragma unroll
        for (int q = 0; q < 16; q++) {
          cn = fmaf(cb[q].x, cb[q].x, cn); cn = fmaf(cb[q].y, cb[q].y, cn);
          cn = fmaf(cb[q].z, cb[q].z, cn); cn = fmaf(cb[q].w, cb[q].w, cn);
        }
        #pragma unroll
        for (int r = 0; r < RB; r++) {
          const float4* A4 = reinterpret_cast<const float4*>(sm.A[r]);
          float dot = 0.f;
          #pragma unroll
          for (int q = 0; q < 16; q++) {
            const float4 a = A4[q];               // broadcast LDS.128
            dot = fmaf(a.x, cb[q].x, dot); dot = fmaf(a.y, cb[q].y, dot);
            dot = fmaf(a.z, cb[q].z, dot); dot = fmaf(a.w, cb[q].w, dot);
          }
          sm.dist[r][cc] = sm.znorm[r] - 2.f * dot + cn;
        }
      }
    }
    __syncthreads();

    // ---- argmin per row (warp r of 16), lexicographic (d, idx) ----
    const int warp = tid >> 5, lane = tid & 31;
    {
      const int r = warp;
      float best = 3.4e38f; int bi = 0;
      for (int cc = lane; cc < p.VQN; cc += 32) {
        const float d = sm.dist[r][cc];
        if (d < best) { best = d; bi = cc; }
      }
      #pragma unroll
      for (int o = 16; o; o >>= 1) {
        const float ob = __shfl_down_sync(0xffffffffu, best, o);
        const int   oi = __shfl_down_sync(0xffffffffu, bi,   o);
        if (ob < best || (ob == best && oi < bi)) { best = ob; bi = oi; }
      }
      bi = __shfl_sync(0xffffffffu, bi, 0);
      float ls = 0.f;
      for (int k = lane; k < 64; k += 32) {
        const float dq = __ldg(p.codebook + (size_t)bi * 64 + k) - sm.A[r][k];
        ls = fmaf(dq, dq, ls);
      }
      #pragma unroll
      for (int o = 16; o; o >>= 1) ls += __shfl_down_sync(0xffffffffu, ls, o);
      if (lane == 0 && c0 + r < p.NC) {
        g_idx_cls[c0 + r]  = bi;
        g_loss_cls[c0 + r] = ls;
      }
    }
  } else {
    // ================= HEAD PATH: 16 codes =================
    const int q0 = (blockIdx.x - p.nClsBlk) * RB;

    pf(sm.wbuf[0], p.Wa, 64 * 128);
    if (tid < RB * 16) {     // gather 16 codebook rows
      const int r = tid >> 4, col = tid & 15;
      reinterpret_cast<float4*>(sm.A[r])[col] =
          __ldg(reinterpret_cast<const float4*>(p.codebook + (size_t)(q0 + r) * 64) + col);
    }
    cpa_wait0(); __syncthreads();

    pf(sm.wbuf[1], p.Ws, 64 * 128);
    layerQ<64, 128, 2>(sm.A, sm.wbuf[0], p.ba, nullptr, g_tbl_actor, q0, sm);
    cpa_wait0(); __syncthreads();

    pf(sm.wbuf[0], p.Wc1, 64 * 128);
    layerQ<64, 128, 3>(sm.A, sm.wbuf[1], p.bs, nullptr, g_tbl_scale, q0, sm);
    cpa_wait0(); __syncthreads();

    pf(sm.wbuf[1], p.Wc2, 128 * 128);
    layerQ<64, 128, 2>(sm.A, sm.wbuf[0], p.bc1, sm.Bb, nullptr, 0, sm);
    cpa_wait0(); __syncthreads();

    pf(sm.wbuf[0], p.Wc3, 128 * 32);
    layerQ<128, 128, 2>(sm.Bb, sm.wbuf[1], p.bc2, sm.A, nullptr, 0, sm);
    cpa_wait0(); __syncthreads();

    layerQ<128, 32, 2>(sm.A, sm.wbuf[0], p.bc3, sm.Bb, nullptr, 0, sm);

    if (tid < RB) {
      float s = __ldg(p.bc4);
      #pragma unroll
      for (int k = 0; k < 32; k++) s = fmaf(sm.Bb[tid][k], __ldg(p.Wc4 + k), s);
      g_tbl_crit[q0 + tid] = s;
    }
  }
}

// ====== gather: column-sliced smem tables; grid = nRowTiles x 4 col-groups ====
__global__ void __launch_bounds__(NTG) acsq_gather(Params p, float scale)
{
  extern __shared__ char smraw[];
  SmemG& sm = *reinterpret_cast<SmemG*>(smraw);
  const int tid = threadIdx.x;
  const int cg = blockIdx.x & 3;                 // column group (32 cols)
  const int rt = blockIdx.x >> 2;                // row tile
  const size_t row0 = (size_t)rt * GROWS;
  const int c0 = cg * 32;

  if (tid == 0) sm.lastblk = 0;

  // stage 32-column slices of both tables (cp.async, 128 KB)
  for (int i = tid; i < 512 * 8; i += NTG) {
    const int row = i >> 3, q = i & 7;
    cpa16(&sm.sA[row * 32 + q * 4], &g_tbl_actor[row * 128 + c0 + q * 4]);
    cpa16(&sm.sS[row * 32 + q * 4], &g_tbl_scale[row * 128 + c0 + q * 4]);
  }
  cpa_commit();

  // codes for this tile (+ idx/critic/loss on col-group 0) while cp.async flies
  float lp = 0.f;
  for (int i = tid; i < GROWS; i += NTG) {
    const size_t b = row0 + i;
    short code = 0;
    if (b < (size_t)p.B) {
      const int o = p.obs[b];
      const int cd = g_idx_cls[o];
      code = (short)cd;
      if (cg == 0) {
        p.out_idx[b]    = (float)cd;
        p.out_critic[b] = g_tbl_crit[cd];
        lp += g_loss_cls[o];
      }
    }
    sm.codes[i] = code;
  }
  if (cg == 0) {
    #pragma unroll
    for (int o = 16; o; o >>= 1) lp += __shfl_down_sync(0xffffffffu, lp, o);
    if ((tid & 31) == 0) sm.red[tid >> 5] = lp;
  }
  __syncthreads();
  if (cg == 0 && tid == 0) {
    float t = 0.f;
    #pragma unroll
    for (int w = 0; w < 8; w++) t += sm.red[w];
    g_partials[rt] = t;
    __threadfence();
    sm.lastblk = (atomicAdd(&g_ticket, 1u) == (unsigned)(p.nRowTiles - 1)) ? 1 : 0;
  }
  cpa_wait0();
  __syncthreads();

  // main copy: smem table slice -> global output (writes only hit LTS)
  const float4* sA4 = reinterpret_cast<const float4*>(sm.sA);
  const float4* sS4 = reinterpret_cast<const float4*>(sm.sS);
  float4* oa = reinterpret_cast<float4*>(p.out_actor);
  float4* os = reinterpret_cast<float4*>(p.out_scale);
  #pragma unroll 4
  for (int i = tid; i < GROWS * 8; i += NTG) {
    const int r = i >> 3, q = i & 7;
    const size_t b = row0 + r;
    if (b < (size_t)p.B) {
      const int cd = sm.codes[r];
      oa[b * 32 + cg * 8 + q] = sA4[cd * 8 + q];
      os[b * 32 + cg * 8 + q] = sS4[cd * 8 + q];
    }
  }

  if (sm.lastblk) {
    float v = 0.f;
    for (int i = tid; i < p.nRowTiles; i += NTG) v += g_partials[i];  // fixed order
    sm.s[tid] = v;
    __syncthreads();
    for (int o = NTG / 2; o > 0; o >>= 1) {
      if (tid < o) sm.s[tid] += sm.s[tid + o];
      __syncthreads();
    }
    if (tid == 0) { *p.out_loss = sm.s[0] * scale; g_ticket = 0u; }
  }
}

extern "C" void kernel_launch(void* const* d_in, const int* in_sizes, int n_in,
                              void* d_out, int out_size)
{
  Params p;
  p.obs      = (const int*)d_in[0];
  p.embed    = (const float*)d_in[1];
  p.W1  = (const float*)d_in[2];  p.b1  = (const float*)d_in[3];
  p.W2  = (const float*)d_in[4];  p.b2  = (const float*)d_in[5];
  p.W3  = (const float*)d_in[6];  p.b3  = (const float*)d_in[7];
  p.Wp  = (const float*)d_in[8];  p.bp  = (const float*)d_in[9];
  p.codebook = (const float*)d_in[10];
  p.Wa  = (const float*)d_in[11]; p.ba  = (const float*)d_in[12];
  p.Ws  = (const float*)d_in[13]; p.bs  = (const float*)d_in[14];
  p.Wc1 = (const float*)d_in[15]; p.bc1 = (const float*)d_in[16];
  p.Wc2 = (const float*)d_in[17]; p.bc2 = (const float*)d_in[18];
  p.Wc3 = (const float*)d_in[19]; p.bc3 = (const float*)d_in[20];
  p.Wc4 = (const float*)d_in[21]; p.bc4 = (const float*)d_in[22];

  const int B   = in_sizes[0];
  const int NC  = in_sizes[1] / 128;   // embed is [NC, 128]
  const int VQN = in_sizes[10] / 64;   // codebook is [VQN, 64]
  p.B = B; p.NC = NC; p.VQN = VQN;
  p.nClsBlk  = (NC + RB - 1) / RB;
  p.nRowTiles = (B + GROWS - 1) / GROWS;

  float* out = (float*)d_out;
  p.out_actor  = out;                                  // [B,128]
  p.out_scale  = out + (size_t)B * 128;                // [B,128]
  p.out_critic = out + (size_t)2 * B * 128;            // [B]
  p.out_loss   = out + (size_t)2 * B * 128 + B;        // scalar
  p.out_idx    = out + (size_t)2 * B * 128 + B + 1;    // [B] as float

  const int headBlk = (VQN + RB - 1) / RB;
  cudaFuncSetAttribute(acsq_ab, cudaFuncAttributeMaxDynamicSharedMemorySize,
                       (int)sizeof(SmemAB));
  cudaFuncSetAttribute(acsq_gather, cudaFuncAttributeMaxDynamicSharedMemorySize,
                       (int)sizeof(SmemG));
  acsq_ab<<<p.nClsBlk + headBlk, NTA, sizeof(SmemAB)>>>(p);
  acsq_gather<<<p.nRowTiles * 4, NTG, sizeof(SmemG)>>>(p, 1.25f / ((float)B * 64.f));
}